// round 17
// baseline (speedup 1.0000x reference)
#include <cuda_runtime.h>

// Polar decomposition of A = rotation[n] @ mat.
// R16 math (best 25.1us) with FOUR INDEPENDENT WARPS per CTA (TPB=128):
// each warp owns a private 64-matrix tile + private smem slice, __syncwarp
// only (no cross-warp coupling) -> 4x fewer CTAs, lifting the CTA-slot /
// churn limit that pinned achieved occupancy at 45% with TPB=32.
//  head: 3 det-scaled Newton steps (g via bit trick; polish only on step 3)
//  tail: plain Newton, free |det(X_in)|-1 < 2.5e-2 test-after-step.
//  cofactors: sub.rn.f32x2 (alu pipe unloaded).

#define TPB 128
#define WARPS_PER_CTA 4
#define MATS_PER_WARP 64
typedef unsigned long long u64;

__device__ __forceinline__ u64 f2pack(float lo, float hi) {
    u64 r; asm("mov.b64 %0, {%1, %2};" : "=l"(r) : "f"(lo), "f"(hi)); return r;
}
__device__ __forceinline__ void f2unpack(u64 v, float& lo, float& hi) {
    asm("mov.b64 {%0, %1}, %2;" : "=f"(lo), "=f"(hi) : "l"(v));
}
__device__ __forceinline__ u64 f2mul(u64 a, u64 b) {
    u64 d; asm("mul.rn.f32x2 %0, %1, %2;" : "=l"(d) : "l"(a), "l"(b)); return d;
}
__device__ __forceinline__ u64 f2sub(u64 a, u64 b) {
    u64 d; asm("sub.rn.f32x2 %0, %1, %2;" : "=l"(d) : "l"(a), "l"(b)); return d;
}
__device__ __forceinline__ u64 f2fma(u64 a, u64 b, u64 c) {
    u64 d; asm("fma.rn.f32x2 %0, %1, %2, %3;" : "=l"(d) : "l"(a), "l"(b), "l"(c)); return d;
}
__device__ __forceinline__ float rcp_fast(float x) {
    float r; asm("rcp.approx.f32 %0, %1;" : "=f"(r) : "f"(x)); return r;
}

__device__ __forceinline__ float invcbrt0(float x) {
    int i = __float_as_int(x);
    i = 0x54A2FA8C - i / 3;
    return __int_as_float(i);
}
__device__ __forceinline__ float invcbrt1(float x) {
    float y = invcbrt0(x);
    const float y3 = y * y * y;
    return y * 0.33333333f * fmaf(-x, y3, 4.0f);
}

struct P2 { u64 x0,x1,x2,x3,x4,x5,x6,x7,x8; };

__device__ __forceinline__ void cof_det(const P2& X, u64 C[9], u64& det) {
    C[0] = f2sub(f2mul(X.x4, X.x8), f2mul(X.x5, X.x7));
    C[1] = f2sub(f2mul(X.x5, X.x6), f2mul(X.x3, X.x8));
    C[2] = f2sub(f2mul(X.x3, X.x7), f2mul(X.x4, X.x6));
    C[3] = f2sub(f2mul(X.x2, X.x7), f2mul(X.x1, X.x8));
    C[4] = f2sub(f2mul(X.x0, X.x8), f2mul(X.x2, X.x6));
    C[5] = f2sub(f2mul(X.x1, X.x6), f2mul(X.x0, X.x7));
    C[6] = f2sub(f2mul(X.x1, X.x5), f2mul(X.x2, X.x4));
    C[7] = f2sub(f2mul(X.x2, X.x3), f2mul(X.x0, X.x5));
    C[8] = f2sub(f2mul(X.x0, X.x4), f2mul(X.x1, X.x3));
    det  = f2fma(X.x0, C[0], f2fma(X.x1, C[1], f2mul(X.x2, C[2])));
}

__device__ __forceinline__ void apply(P2& X, const u64 C[9], u64 hg, u64 rr) {
    X.x0 = f2fma(rr, C[0], f2mul(hg, X.x0));
    X.x1 = f2fma(rr, C[1], f2mul(hg, X.x1));
    X.x2 = f2fma(rr, C[2], f2mul(hg, X.x2));
    X.x3 = f2fma(rr, C[3], f2mul(hg, X.x3));
    X.x4 = f2fma(rr, C[4], f2mul(hg, X.x4));
    X.x5 = f2fma(rr, C[5], f2mul(hg, X.x5));
    X.x6 = f2fma(rr, C[6], f2mul(hg, X.x6));
    X.x7 = f2fma(rr, C[7], f2mul(hg, X.x7));
    X.x8 = f2fma(rr, C[8], f2mul(hg, X.x8));
}

template <bool POLISH>
__device__ __forceinline__ void step_scaled(P2& X) {
    u64 C[9], det;
    cof_det(X, C, det);
    float dl, dh;
    f2unpack(det, dl, dh);
    const float al = fmaxf(fabsf(dl), 1e-30f);
    const float ah = fmaxf(fabsf(dh), 1e-30f);
    const float gl = POLISH ? invcbrt1(al) : invcbrt0(al);
    const float gh = POLISH ? invcbrt1(ah) : invcbrt0(ah);
    const float rl = copysignf(0.5f * gl * gl, dl);
    const float rh = copysignf(0.5f * gh * gh, dh);
    apply(X, C, f2pack(0.5f * gl, 0.5f * gh), f2pack(rl, rh));
}

__device__ __forceinline__ bool step_plain(P2& X) {
    u64 C[9], det;
    cof_det(X, C, det);
    float dl, dh;
    f2unpack(det, dl, dh);
    const float rl = 0.5f * rcp_fast(dl);
    const float rh = 0.5f * rcp_fast(dh);
    apply(X, C, 0x3F0000003F000000ULL /*(0.5f,0.5f)*/, f2pack(rl, rh));
    return (fabsf(fabsf(dl) - 1.0f) < 2.5e-2f) &&
           (fabsf(fabsf(dh) - 1.0f) < 2.5e-2f);
}

__device__ __forceinline__ void iterate(P2& X) {
    step_scaled<false>(X);
    step_scaled<false>(X);
    step_scaled<true>(X);
    #pragma unroll 1
    for (int it = 0; it < 9; ++it) {
        const bool ok = step_plain(X);
        if (__all_sync(0xffffffffu, ok)) break;
    }
}

__device__ __forceinline__ void init_matmul(P2& X, const u64 R[9], const float* mat) {
    u64 M[9];
    #pragma unroll
    for (int k = 0; k < 9; ++k) { const float m = __ldg(mat + k); M[k] = f2pack(m, m); }
    X.x0 = f2fma(R[0], M[0], f2fma(R[1], M[3], f2mul(R[2], M[6])));
    X.x1 = f2fma(R[0], M[1], f2fma(R[1], M[4], f2mul(R[2], M[7])));
    X.x2 = f2fma(R[0], M[2], f2fma(R[1], M[5], f2mul(R[2], M[8])));
    X.x3 = f2fma(R[3], M[0], f2fma(R[4], M[3], f2mul(R[5], M[6])));
    X.x4 = f2fma(R[3], M[1], f2fma(R[4], M[4], f2mul(R[5], M[7])));
    X.x5 = f2fma(R[3], M[2], f2fma(R[4], M[5], f2mul(R[5], M[8])));
    X.x6 = f2fma(R[6], M[0], f2fma(R[7], M[3], f2mul(R[8], M[6])));
    X.x7 = f2fma(R[6], M[1], f2fma(R[7], M[4], f2mul(R[8], M[7])));
    X.x8 = f2fma(R[6], M[2], f2fma(R[7], M[5], f2mul(R[8], M[8])));
}

// ---- HOT kernel: 4 independent warps/CTA, full 64-matrix warp-tiles ----
__global__ void __launch_bounds__(TPB)
polar_full_kernel(const float* __restrict__ rot,
                  const float* __restrict__ mat,
                  float* __restrict__ out,
                  float* __restrict__ logdet,
                  int n_tiles)
{
    __shared__ float smem[WARPS_PER_CTA][MATS_PER_WARP * 9];
    const int lid  = threadIdx.x & 31;
    const int wid  = threadIdx.x >> 5;
    const int tile = blockIdx.x * WARPS_PER_CTA + wid;
    if (tile >= n_tiles) return;

    float* s = smem[wid];
    const int base = tile * MATS_PER_WARP;

    // coalesced load: 4 full float4 rounds + 16-thread round (144 float4)
    {
        const float4* g4 = reinterpret_cast<const float4*>(rot + (size_t)base * 9);
        float4* s4 = reinterpret_cast<float4*>(s);
        #pragma unroll
        for (int j = 0; j < 4; ++j) s4[lid + 32 * j] = g4[lid + 32 * j];
        if (lid < 16) s4[128 + lid] = g4[128 + lid];
    }
    __syncwarp();

    const int olo = 2 * lid * 9, ohi = olo + 9;
    u64 R[9];
    #pragma unroll
    for (int k = 0; k < 9; ++k) R[k] = f2pack(s[olo + k], s[ohi + k]);
    __syncwarp();

    P2 X;
    init_matmul(X, R, mat);
    iterate(X);

    {
        float a, b;
        f2unpack(X.x0, a, b); s[olo + 0] = a; s[ohi + 0] = b;
        f2unpack(X.x1, a, b); s[olo + 1] = a; s[ohi + 1] = b;
        f2unpack(X.x2, a, b); s[olo + 2] = a; s[ohi + 2] = b;
        f2unpack(X.x3, a, b); s[olo + 3] = a; s[ohi + 3] = b;
        f2unpack(X.x4, a, b); s[olo + 4] = a; s[ohi + 4] = b;
        f2unpack(X.x5, a, b); s[olo + 5] = a; s[ohi + 5] = b;
        f2unpack(X.x6, a, b); s[olo + 6] = a; s[ohi + 6] = b;
        f2unpack(X.x7, a, b); s[olo + 7] = a; s[ohi + 7] = b;
        f2unpack(X.x8, a, b); s[olo + 8] = a; s[ohi + 8] = b;
    }
    __syncwarp();
    {
        float4* g4 = reinterpret_cast<float4*>(out + (size_t)base * 9);
        const float4* s4 = reinterpret_cast<const float4*>(s);
        #pragma unroll
        for (int j = 0; j < 4; ++j) g4[lid + 32 * j] = s4[lid + 32 * j];
        if (lid < 16) g4[128 + lid] = s4[128 + lid];
    }
    *reinterpret_cast<float2*>(logdet + base + 2 * lid) = make_float2(0.f, 0.f);
}

// ---- generic kernel: handles the (possibly empty) remainder ----
__global__ void __launch_bounds__(32)
polar_rem_kernel(const float* __restrict__ rot,
                 const float* __restrict__ mat,
                 float* __restrict__ out,
                 float* __restrict__ logdet,
                 int start, int N)
{
    __shared__ float s[32 * 18];
    const int tid  = threadIdx.x;
    const int base = start;
    const int nmat = N - base;
    const int nflt = nmat * 9;

    {
        const float* g = rot + (size_t)base * 9;
        const int nv = nflt >> 2;
        const float4* g4 = reinterpret_cast<const float4*>(g);
        float4* s4 = reinterpret_cast<float4*>(s);
        for (int i = tid; i < nv; i += 32) s4[i] = g4[i];
        for (int i = (nv << 2) + tid; i < nflt; i += 32) s[i] = g[i];
    }
    __syncwarp();

    const bool vlo = (base + 2 * tid)     < N;
    const bool vhi = (base + 2 * tid + 1) < N;
    const int olo = 2 * tid * 9, ohi = olo + 9;
    u64 R[9];
    #pragma unroll
    for (int k = 0; k < 9; ++k) {
        const float idv = (k == 0 || k == 4 || k == 8) ? 1.0f : 0.0f;
        R[k] = f2pack(vlo ? s[olo + k] : idv, vhi ? s[ohi + k] : idv);
    }
    __syncwarp();

    P2 X;
    init_matmul(X, R, mat);
    iterate(X);

    {
        float a, b;
        f2unpack(X.x0, a, b); s[olo + 0] = a; s[ohi + 0] = b;
        f2unpack(X.x1, a, b); s[olo + 1] = a; s[ohi + 1] = b;
        f2unpack(X.x2, a, b); s[olo + 2] = a; s[ohi + 2] = b;
        f2unpack(X.x3, a, b); s[olo + 3] = a; s[ohi + 3] = b;
        f2unpack(X.x4, a, b); s[olo + 4] = a; s[ohi + 4] = b;
        f2unpack(X.x5, a, b); s[olo + 5] = a; s[ohi + 5] = b;
        f2unpack(X.x6, a, b); s[olo + 6] = a; s[ohi + 6] = b;
        f2unpack(X.x7, a, b); s[olo + 7] = a; s[ohi + 7] = b;
        f2unpack(X.x8, a, b); s[olo + 8] = a; s[ohi + 8] = b;
    }
    __syncwarp();
    {
        float* g = out + (size_t)base * 9;
        const int nv = nflt >> 2;
        const float4* s4 = reinterpret_cast<const float4*>(s);
        float4* g4 = reinterpret_cast<float4*>(g);
        for (int i = tid; i < nv; i += 32) g4[i] = s4[i];
        for (int i = (nv << 2) + tid; i < nflt; i += 32) g[i] = s[i];
    }
    for (int i = tid; i < nmat; i += 32) logdet[base + i] = 0.0f;
}

__global__ void zero_tail_kernel(float* __restrict__ p, long long n)
{
    long long i = (long long)blockIdx.x * blockDim.x + threadIdx.x;
    if (i < n) p[i] = 0.0f;
}

extern "C" void kernel_launch(void* const* d_in, const int* in_sizes, int n_in,
                              void* d_out, int out_size)
{
    const float* rot = (const float*)d_in[0];
    const float* mat = (const float*)d_in[1];
    float* out = (float*)d_out;

    const int N = in_sizes[0] / 9;
    float* logdet = out + (size_t)N * 9;

    const int n_tiles = N / MATS_PER_WARP;                 // full 64-mat tiles
    if (n_tiles > 0) {
        const int blocks = (n_tiles + WARPS_PER_CTA - 1) / WARPS_PER_CTA;
        polar_full_kernel<<<blocks, TPB>>>(rot, mat, out, logdet, n_tiles);
    }
    const int rem_start = n_tiles * MATS_PER_WARP;
    if (rem_start < N)
        polar_rem_kernel<<<1, 32>>>(rot, mat, out, logdet, rem_start, N);

    const long long used = 10LL * N;
    if ((long long)out_size > used) {
        const long long extra = (long long)out_size - used;
        const int zb = (int)((extra + 255) / 256);
        zero_tail_kernel<<<zb, 256>>>(out + used, extra);
    }
}